// round 14
// baseline (speedup 1.0000x reference)
#include <cuda_runtime.h>
#include <cstdint>
#include <cstddef>

#define DI __device__ __forceinline__

namespace {
constexpr int IN_DIM  = 1024;
constexpr int MEM_DIM = 512;
constexpr int N_NODES = 100000;
constexpr int BATCH   = 65536;

constexpr int BM = 128, BN = 256, BK = 64;
constexpr int MT = BATCH / BM;     // 512
constexpr int NT = MEM_DIM / BN;   // 2
constexpr int KC = IN_DIM / BK;    // 16
constexpr int THREADS = 256;       // 8 warps: 2 (M) x 4 (N), warp tile 64x64
constexpr int STAGES = 2;
constexpr int GEMM_BLOCKS = 2 * MT * NT;   // 2048
constexpr int NTICK = 37;                  // CTAs that also perform the init copy

constexpr long long NODE4 = (long long)N_NODES * MEM_DIM / 4;   // 12,800,000 float4
constexpr long long TOT4  = NODE4 + 500LL * MEM_DIM / 4;        // 12,864,000 float4
constexpr long long SLICE = (TOT4 + NTICK - 1) / NTICK;         // per-ticket float4 count

// smem per stage: A[128 rows][256B] + B[256 rows][256B]; a row = 64 fp32 (one BK chunk),
// 16B units XOR-swizzled by (row&7) for conflict-free ldmatrix.
constexpr int SA_BYTES    = BM * 256;               // 32 KB
constexpr int SB_BYTES    = BN * 256;               // 64 KB
constexpr int STAGE_BYTES = SA_BYTES + SB_BYTES;    // 96 KB
constexpr int SMEM_BYTES  = STAGES * STAGE_BYTES;   // 192 KB
}  // namespace

// single-kernel init/gate bookkeeping (zero-init; self-resetting every run)
__device__ unsigned int g_ticket = 0;   // init-slice tickets
__device__ unsigned int g_done   = 0;   // completed init slices
__device__ unsigned int g_fin    = 0;   // finished CTAs (for reset)

// ---------------- base-ISA helpers (NO tcgen05 — target is plain sm_103) ----------------

DI uint32_t smem_u32(const void* p) {
    uint32_t a;
    asm("{ .reg .u64 t; cvta.to.shared.u64 t, %1; cvt.u32.u64 %0, t; }" : "=r"(a) : "l"(p));
    return a;
}

DI uint32_t f2tf32(uint32_t fbits) {   // round-to-nearest tf32 on raw fp32 bits
    uint32_t r;
    asm("cvt.rna.tf32.f32 %0, %1;" : "=r"(r) : "r"(fbits));
    return r;
}

DI void ldsm_x4(uint32_t* r, uint32_t addr) {
    asm volatile("ldmatrix.sync.aligned.m8n8.x4.shared.b16 {%0,%1,%2,%3}, [%4];"
                 : "=r"(r[0]), "=r"(r[1]), "=r"(r[2]), "=r"(r[3]) : "r"(addr));
}

DI void mma_tf32(float* c, const uint32_t* a, const uint32_t* b) {
    asm volatile(
        "mma.sync.aligned.m16n8k8.row.col.f32.tf32.tf32.f32 "
        "{%0,%1,%2,%3}, {%4,%5,%6,%7}, {%8,%9}, {%0,%1,%2,%3};"
        : "+f"(c[0]), "+f"(c[1]), "+f"(c[2]), "+f"(c[3])
        : "r"(a[0]), "r"(a[1]), "r"(a[2]), "r"(a[3]), "r"(b[0]), "r"(b[1]));
}

DI void cp_async16(uint32_t smem_addr, const void* gptr) {
    asm volatile("cp.async.cg.shared.global [%0], [%1], 16;"
                 :: "r"(smem_addr), "l"(gptr));
}
DI void cp_commit() { asm volatile("cp.async.commit_group;"); }
DI void cp_wait1()  { asm volatile("cp.async.wait_group 1;"); }

DI void red_add_v2(float* gaddr, float x, float y) {   // vector reduction, no return (sm_90+)
    asm volatile("red.global.add.v2.f32 [%0], {%1, %2};"
                 :: "l"(gaddr), "f"(x), "f"(y) : "memory");
}

// ---------------- fused kernel: ticket-init + TF32 mma.sync GEMM + gated vector-RED scatter ----------------

__global__ void __launch_bounds__(THREADS, 1)
gemm_scatter_kernel(const float* __restrict__ nodes_emb, const float* __restrict__ rels_emb,
                    const int* __restrict__ nodes_ids, const int* __restrict__ rels_ids,
                    const float* __restrict__ W_node, const float* __restrict__ b_node,
                    const float* __restrict__ W_rel, const float* __restrict__ b_rel,
                    const int* __restrict__ timep,
                    const float4* __restrict__ ent4, const float4* __restrict__ rel4,
                    float* __restrict__ out) {
    extern __shared__ char smem[];
    const uint32_t sb = smem_u32(smem);
    const int tid = threadIdx.x;
    const int lane = tid & 31;
    const int wid = tid >> 5;
    const int wm = wid & 1;      // warp row (2)  -> 64 M rows each
    const int wn = wid >> 1;     // warp col (4)  -> 64 N cols each

    // ---- phase 0: atomic-ticket init (first NTICK CTAs scheduled do the memory copy+scale) ----
    // Deadlock-free by construction: ticket holders are already resident; their slices have no deps.
    __shared__ unsigned int s_ticket;
    if (tid == 0) s_ticket = atomicAdd(&g_ticket, 1u);
    __syncthreads();
    const unsigned int my_ticket = s_ticket;
    if (my_ticket < (unsigned)NTICK) {
        const int t = *timep;
        const float s = (t > 1) ? (float)t / (float)(t + 1) : 1.0f;
        const long long beg = (long long)my_ticket * SLICE;
        const long long end = (beg + SLICE < TOT4) ? beg + SLICE : TOT4;
        float4* out4 = reinterpret_cast<float4*>(out);
        for (long long i = beg + tid; i < end; i += THREADS) {
            float4 v = (i < NODE4) ? ent4[i] : rel4[i - NODE4];
            v.x *= s; v.y *= s; v.z *= s; v.w *= s;
            out4[i] = v;
        }
        __syncthreads();
        if (tid == 0) {
            __threadfence();
            atomicAdd(&g_done, 1u);
        }
    }

    const bool is_rel = (blockIdx.x >= (unsigned)(MT * NT));
    const int bid = is_rel ? (int)blockIdx.x - MT * NT : (int)blockIdx.x;
    const int tile_n = bid & (NT - 1);
    const int tile_m = bid >> 1;

    const float* Aptr = is_rel ? rels_emb : nodes_emb;
    const float* Wptr = is_rel ? W_rel : W_node;
    const float* bias = is_rel ? b_rel : b_node;
    const int*   ids  = is_rel ? rels_ids : nodes_ids;
    float* outhalf = out + (is_rel ? (size_t)N_NODES * MEM_DIM : 0);

    const float* Abase = Aptr + (size_t)(tile_m * BM) * IN_DIM;
    const float* Wbase = Wptr + (size_t)(tile_n * BN) * IN_DIM;

    // ---- cp.async slots: 16 16B-slots per 256B row; k4 = tid&15 is slot-invariant ----
    const int  row0 = tid >> 4;                       // 0..15
    const int  k4   = tid & 15;                       // 0..15
    const uint32_t go0 = (uint32_t)(row0 * IN_DIM + k4 * 4);
    const uint32_t st0 = (uint32_t)(row0 * 256 + ((k4 ^ (row0 & 7)) << 4));

    auto issue_chunk = [&](int kc) {   // always commits (uniform wait arithmetic)
        if (kc < KC) {
            const uint32_t go = go0 + (uint32_t)(kc * BK);
            const uint32_t stg = sb + (uint32_t)((kc & (STAGES - 1)) * STAGE_BYTES);
#pragma unroll
            for (int j = 0; j < 8; ++j)                  // A: 8 slots, stride 16 rows
                cp_async16(stg + st0 + j * 16 * 256, Abase + go + j * 16 * IN_DIM);
#pragma unroll
            for (int j = 0; j < 16; ++j)                 // B: 16 slots
                cp_async16(stg + SA_BYTES + st0 + j * 16 * 256, Wbase + go + j * 16 * IN_DIM);
        }
        cp_commit();
    };

    // ---- ldmatrix address precompute (R7 mapping, 256B row pitch) ----
    const int a_khi = lane >> 4;
    uint32_t a_rowb[4]; int a_r7[4];
#pragma unroll
    for (int mt = 0; mt < 4; ++mt) {
        int row = wm * 64 + mt * 16 + (lane & 7) + ((lane >> 3) & 1) * 8;
        a_rowb[mt] = (uint32_t)(row * 256);
        a_r7[mt] = row & 7;
    }
    const int b_khi = (lane >> 3) & 1;
    uint32_t b_rowb[4]; int b_r7[4];
#pragma unroll
    for (int np = 0; np < 4; ++np) {
        int row = wn * 64 + np * 16 + (lane & 7) + ((lane >> 4) & 1) * 8;
        b_rowb[np] = (uint32_t)(SA_BYTES + row * 256);
        b_r7[np] = row & 7;
    }

    float C[4][8][4];
#pragma unroll
    for (int mt = 0; mt < 4; ++mt)
#pragma unroll
        for (int nt = 0; nt < 8; ++nt)
#pragma unroll
            for (int v = 0; v < 4; ++v) C[mt][nt][v] = 0.0f;

    // ---- prologue: 2 chunks in flight ----
    issue_chunk(0);
    issue_chunk(1);

    // ---- main loop: 16 chunks, 8 ksteps each (R12 body, unchanged) ----
    for (int kc = 0; kc < KC; ++kc) {
        cp_wait1();          // chunk kc complete (chunk kc+1 still outstanding)
        __syncthreads();     // data visible to all warps

        const uint32_t cur = sb + (uint32_t)((kc & (STAGES - 1)) * STAGE_BYTES);
#pragma unroll
        for (int ks = 0; ks < 8; ++ks) {
            uint32_t afr[4][4];
#pragma unroll
            for (int mt = 0; mt < 4; ++mt) {
                uint32_t addr = cur + a_rowb[mt] + (uint32_t)(((2 * ks + a_khi) ^ a_r7[mt]) << 4);
                ldsm_x4(afr[mt], addr);
#pragma unroll
                for (int v = 0; v < 4; ++v) afr[mt][v] = f2tf32(afr[mt][v]);
            }
#pragma unroll
            for (int np = 0; np < 4; ++np) {
                uint32_t bfr[4];
                uint32_t addr = cur + b_rowb[np] + (uint32_t)(((2 * ks + b_khi) ^ b_r7[np]) << 4);
                ldsm_x4(bfr, addr);
#pragma unroll
                for (int v = 0; v < 4; ++v) bfr[v] = f2tf32(bfr[v]);
#pragma unroll
                for (int mt = 0; mt < 4; ++mt) {
                    mma_tf32(C[mt][2 * np],     afr[mt], bfr);
                    mma_tf32(C[mt][2 * np + 1], afr[mt], bfr + 2);
                }
            }
        }
        __syncthreads();     // all warps done reading stage kc&1 before refilling it
        issue_chunk(kc + 2); // writes stage kc&1
    }

    // ---- gate: all NTICK init slices complete before scatter (gate is resident-CTA-only) ----
    if (tid == 0) {
        while (atomicAdd(&g_done, 0u) < (unsigned)NTICK) { __nanosleep(128); }
    }
    __syncthreads();
    __threadfence();

    // ---- epilogue: out[id[m]] += (C + bias) / (t+1), vector RED scatter (v2.f32) ----
    const int t = *timep;
    const float inv = 1.0f / (float)(t + 1);
    const int g = lane >> 2;
    const int tg = lane & 3;

    float* p[8];
#pragma unroll
    for (int mt = 0; mt < 4; ++mt) {
        int r0 = tile_m * BM + wm * 64 + mt * 16 + g;
        p[2 * mt]     = outhalf + (size_t)ids[r0] * MEM_DIM;
        p[2 * mt + 1] = outhalf + (size_t)ids[r0 + 8] * MEM_DIM;
    }
#pragma unroll
    for (int nt = 0; nt < 8; ++nt) {
        const int c = tile_n * BN + wn * 64 + nt * 8 + tg * 2;
        const float2 bv = *reinterpret_cast<const float2*>(bias + c);
#pragma unroll
        for (int mt = 0; mt < 4; ++mt) {
            red_add_v2(p[2 * mt] + c,     (C[mt][nt][0] + bv.x) * inv, (C[mt][nt][1] + bv.y) * inv);
            red_add_v2(p[2 * mt + 1] + c, (C[mt][nt][2] + bv.x) * inv, (C[mt][nt][3] + bv.y) * inv);
        }
    }

    // ---- reset for next graph replay: last CTA to finish (everyone already passed the gate) ----
    __syncthreads();
    if (tid == 0) {
        unsigned int old = atomicAdd(&g_fin, 1u);
        if (old == (unsigned)GEMM_BLOCKS - 1u) {
            atomicExch(&g_ticket, 0u);
            atomicExch(&g_done, 0u);
            atomicExch(&g_fin, 0u);
        }
    }
}

// ---------------- launch ----------------

extern "C" void kernel_launch(void* const* d_in, const int* in_sizes, int n_in,
                              void* d_out, int out_size) {
    const float* nodes_emb = (const float*)d_in[0];
    const float* rels_emb  = (const float*)d_in[1];
    const int*   nodes_ids = (const int*)d_in[2];
    const int*   rels_ids  = (const int*)d_in[3];
    const float* ent_mem   = (const float*)d_in[4];
    const float* rel_mem   = (const float*)d_in[5];
    const float* W_node    = (const float*)d_in[6];
    const float* b_node    = (const float*)d_in[7];
    const float* W_rel     = (const float*)d_in[8];
    const float* b_rel     = (const float*)d_in[9];
    const int*   timep     = (const int*)d_in[10];
    float* out = (float*)d_out;

    static bool attr_set = false;
    if (!attr_set) {
        cudaFuncSetAttribute(gemm_scatter_kernel,
                             cudaFuncAttributeMaxDynamicSharedMemorySize, SMEM_BYTES);
        attr_set = true;
    }

    // single fused kernel: ticket-init + GEMM + gated scatter (default stream only)
    gemm_scatter_kernel<<<GEMM_BLOCKS, THREADS, SMEM_BYTES>>>(
        nodes_emb, rels_emb, nodes_ids, rels_ids,
        W_node, b_node, W_rel, b_rel, timep,
        (const float4*)ent_mem, (const float4*)rel_mem, out);
}

// round 15
// speedup vs baseline: 1.2199x; 1.2199x over previous
#include <cuda_runtime.h>
#include <cstdint>
#include <cstddef>

#define DI __device__ __forceinline__

namespace {
constexpr int IN_DIM  = 1024;
constexpr int MEM_DIM = 512;
constexpr int N_NODES = 100000;
constexpr int BATCH   = 65536;

constexpr int BM = 128, BN = 256, BK = 64;
constexpr int MT = BATCH / BM;     // 512
constexpr int NT = MEM_DIM / BN;   // 2
constexpr int KC = IN_DIM / BK;    // 16
constexpr int THREADS = 256;       // 8 warps: 2 (M) x 4 (N), warp tile 64x64
constexpr int STAGES = 2;
constexpr int NTILES  = 2 * MT * NT;   // 2048
constexpr int PERSIST = 152;           // >= SM count; work-stealing handles the rest

// smem per stage: A[128 rows][256B] + B[256 rows][256B]; a row = 64 fp32 (one BK chunk),
// 16B units XOR-swizzled by (row&7) for conflict-free ldmatrix.
constexpr int SA_BYTES    = BM * 256;               // 32 KB
constexpr int SB_BYTES    = BN * 256;               // 64 KB
constexpr int STAGE_BYTES = SA_BYTES + SB_BYTES;    // 96 KB
constexpr int SMEM_BYTES  = STAGES * STAGE_BYTES;   // 192 KB
}  // namespace

// persistent-kernel bookkeeping (zero-init; self-resetting every run)
__device__ unsigned int g_tile = 0;
__device__ unsigned int g_fin  = 0;

// ---------------- base-ISA helpers (NO tcgen05 — target is plain sm_103) ----------------

DI uint32_t smem_u32(const void* p) {
    uint32_t a;
    asm("{ .reg .u64 t; cvta.to.shared.u64 t, %1; cvt.u32.u64 %0, t; }" : "=r"(a) : "l"(p));
    return a;
}

DI uint32_t f2tf32(uint32_t fbits) {   // round-to-nearest tf32 on raw fp32 bits
    uint32_t r;
    asm("cvt.rna.tf32.f32 %0, %1;" : "=r"(r) : "r"(fbits));
    return r;
}

DI void ldsm_x4(uint32_t* r, uint32_t addr) {
    asm volatile("ldmatrix.sync.aligned.m8n8.x4.shared.b16 {%0,%1,%2,%3}, [%4];"
                 : "=r"(r[0]), "=r"(r[1]), "=r"(r[2]), "=r"(r[3]) : "r"(addr));
}

DI void mma_tf32(float* c, const uint32_t* a, const uint32_t* b) {
    asm volatile(
        "mma.sync.aligned.m16n8k8.row.col.f32.tf32.tf32.f32 "
        "{%0,%1,%2,%3}, {%4,%5,%6,%7}, {%8,%9}, {%0,%1,%2,%3};"
        : "+f"(c[0]), "+f"(c[1]), "+f"(c[2]), "+f"(c[3])
        : "r"(a[0]), "r"(a[1]), "r"(a[2]), "r"(a[3]), "r"(b[0]), "r"(b[1]));
}

DI void cp_async16(uint32_t smem_addr, const void* gptr) {
    asm volatile("cp.async.cg.shared.global [%0], [%1], 16;"
                 :: "r"(smem_addr), "l"(gptr));
}
DI void cp_commit() { asm volatile("cp.async.commit_group;"); }
DI void cp_wait1()  { asm volatile("cp.async.wait_group 1;"); }

DI void red_add_v2(float* gaddr, float x, float y) {   // vector reduction, no return (sm_90+)
    asm volatile("red.global.add.v2.f32 [%0], {%1, %2};"
                 :: "l"(gaddr), "f"(x), "f"(y) : "memory");
}

// ---------------- Kernel 1: out = concat(entity_mem, rel_mem) * (t>1 ? t/(t+1) : 1) ----------------

__global__ void init_out_kernel(const float4* __restrict__ ent, const float4* __restrict__ rel,
                                const int* __restrict__ timep, float4* __restrict__ out) {
    const long long NODE4 = (long long)N_NODES * MEM_DIM / 4;
    const long long TOT4  = NODE4 + 500LL * MEM_DIM / 4;
    long long i = (long long)blockIdx.x * blockDim.x + threadIdx.x;
    if (i >= TOT4) return;
    int t = *timep;
    float s = (t > 1) ? (float)t / (float)(t + 1) : 1.0f;
    float4 v = (i < NODE4) ? ent[i] : rel[i - NODE4];
    v.x *= s; v.y *= s; v.z *= s; v.w *= s;
    out[i] = v;
}

// ---------------- Kernel 2: persistent TF32 mma.sync GEMM, cross-tile pipelined ----------------

__global__ void __launch_bounds__(THREADS, 1)
gemm_scatter_kernel(const float* __restrict__ nodes_emb, const float* __restrict__ rels_emb,
                    const int* __restrict__ nodes_ids, const int* __restrict__ rels_ids,
                    const float* __restrict__ W_node, const float* __restrict__ b_node,
                    const float* __restrict__ W_rel, const float* __restrict__ b_rel,
                    const int* __restrict__ timep, float* __restrict__ out) {
    extern __shared__ char smem[];
    const uint32_t sb = smem_u32(smem);
    const int tid = threadIdx.x;
    const int lane = tid & 31;
    const int wid = tid >> 5;
    const int wm = wid & 1;      // warp row (2)  -> 64 M rows each
    const int wn = wid >> 1;     // warp col (4)  -> 64 N cols each

    __shared__ unsigned int s_tick;

    // ---- tile-independent precompute ----
    const int  row0 = tid >> 4;
    const int  k4   = tid & 15;
    const uint32_t go0 = (uint32_t)(row0 * IN_DIM + k4 * 4);
    const uint32_t st0 = (uint32_t)(row0 * 256 + ((k4 ^ (row0 & 7)) << 4));

    const int a_khi = lane >> 4;
    uint32_t a_rowb[4]; int a_r7[4];
#pragma unroll
    for (int mt = 0; mt < 4; ++mt) {
        int row = wm * 64 + mt * 16 + (lane & 7) + ((lane >> 3) & 1) * 8;
        a_rowb[mt] = (uint32_t)(row * 256);
        a_r7[mt] = row & 7;
    }
    const int b_khi = (lane >> 3) & 1;
    uint32_t b_rowb[4]; int b_r7[4];
#pragma unroll
    for (int np = 0; np < 4; ++np) {
        int row = wn * 64 + np * 16 + (lane & 7) + ((lane >> 4) & 1) * 8;
        b_rowb[np] = (uint32_t)(SA_BYTES + row * 256);
        b_r7[np] = row & 7;
    }

    const int t = *timep;
    const float inv = 1.0f / (float)(t + 1);
    const int g = lane >> 2;
    const int tg = lane & 3;

    float C[4][8][4];
#pragma unroll
    for (int mt = 0; mt < 4; ++mt)
#pragma unroll
        for (int nt = 0; nt < 8; ++nt)
#pragma unroll
            for (int v = 0; v < 4; ++v) C[mt][nt][v] = 0.0f;

    // issue one BK-chunk of a tile (always commits — keeps wait1 arithmetic uniform)
    auto issue = [&](const float* Ab, const float* Wb, int kc) {
        const uint32_t go = go0 + (uint32_t)(kc * BK);
        const uint32_t stg = sb + (uint32_t)((kc & (STAGES - 1)) * STAGE_BYTES);
#pragma unroll
        for (int j = 0; j < 8; ++j)
            cp_async16(stg + st0 + j * 16 * 256, Ab + go + j * 16 * IN_DIM);
#pragma unroll
        for (int j = 0; j < 16; ++j)
            cp_async16(stg + SA_BYTES + st0 + j * 16 * 256, Wb + go + j * 16 * IN_DIM);
        cp_commit();
    };

    // compute one BK-chunk from a stage (R12 body, unchanged)
    auto compute = [&](int stage_par) {
        const uint32_t cur = sb + (uint32_t)(stage_par * STAGE_BYTES);
#pragma unroll
        for (int ks = 0; ks < 8; ++ks) {
            uint32_t afr[4][4];
#pragma unroll
            for (int mt = 0; mt < 4; ++mt) {
                uint32_t addr = cur + a_rowb[mt] + (uint32_t)(((2 * ks + a_khi) ^ a_r7[mt]) << 4);
                ldsm_x4(afr[mt], addr);
#pragma unroll
                for (int v = 0; v < 4; ++v) afr[mt][v] = f2tf32(afr[mt][v]);
            }
#pragma unroll
            for (int np = 0; np < 4; ++np) {
                uint32_t bfr[4];
                uint32_t addr = cur + b_rowb[np] + (uint32_t)(((2 * ks + b_khi) ^ b_r7[np]) << 4);
                ldsm_x4(bfr, addr);
#pragma unroll
                for (int v = 0; v < 4; ++v) bfr[v] = f2tf32(bfr[v]);
#pragma unroll
                for (int mt = 0; mt < 4; ++mt) {
                    mma_tf32(C[mt][2 * np],     afr[mt], bfr);
                    mma_tf32(C[mt][2 * np + 1], afr[mt], bfr + 2);
                }
            }
        }
    };

    // tile context setup
    auto setup = [&](unsigned tt, const float*& Ab, const float*& Wb, const float*& bs,
                     const int*& id, float*& oh, int& tm, int& tn) {
        const bool isr = (tt >= (unsigned)(MT * NT));
        const int bid = isr ? (int)tt - MT * NT : (int)tt;
        tn = bid & (NT - 1);
        tm = bid >> 1;
        const float* Ap = isr ? rels_emb : nodes_emb;
        const float* Wp = isr ? W_rel : W_node;
        bs = isr ? b_rel : b_node;
        id = isr ? rels_ids : nodes_ids;
        oh = out + (isr ? (size_t)N_NODES * MEM_DIM : 0);
        Ab = Ap + (size_t)(tm * BM) * IN_DIM;
        Wb = Wp + (size_t)(tn * BN) * IN_DIM;
    };

    // ---- first ticket ----
    if (tid == 0) s_tick = atomicAdd(&g_tile, 1u);
    __syncthreads();
    unsigned tcur = s_tick;

    if (tcur < (unsigned)NTILES) {
        const float *cA, *cW, *cbias; const int* cids; float* cout; int cm, cn;
        setup(tcur, cA, cW, cbias, cids, cout, cm, cn);
        issue(cA, cW, 0);
        issue(cA, cW, 1);

        for (;;) {
            // chunks 0..13 of the current tile
            for (int kc = 0; kc < KC - 2; ++kc) {
                cp_wait1();
                __syncthreads();
                compute(kc & 1);
                __syncthreads();
                issue(cA, cW, kc + 2);
            }
            // chunk 14: after it, draw the next ticket and start fetching the next tile
            cp_wait1();
            __syncthreads();
            compute(0);
            __syncthreads();
            if (tid == 0) s_tick = atomicAdd(&g_tile, 1u);
            __syncthreads();
            const unsigned tnxt = s_tick;
            const bool nvalid = (tnxt < (unsigned)NTILES);
            const float *nA = nullptr, *nW = nullptr, *nbias = nullptr;
            const int* nids = nullptr; float* nout = nullptr; int nm = 0, nn = 0;
            if (nvalid) {
                setup(tnxt, nA, nW, nbias, nids, nout, nm, nn);
                issue(nA, nW, 0);        // writes stage 0 (chunk 14's stage, just drained)
            } else {
                cp_commit();
            }
            // chunk 15
            cp_wait1();
            __syncthreads();
            compute(1);
            __syncthreads();
            if (nvalid) issue(nA, nW, 1); else cp_commit();

            // ---- epilogue of the current tile (REDs drain under the next tile's fetch) ----
            float* p[8];
#pragma unroll
            for (int mt = 0; mt < 4; ++mt) {
                int r0 = cm * BM + wm * 64 + mt * 16 + g;
                p[2 * mt]     = cout + (size_t)cids[r0] * MEM_DIM;
                p[2 * mt + 1] = cout + (size_t)cids[r0 + 8] * MEM_DIM;
            }
#pragma unroll
            for (int nt = 0; nt < 8; ++nt) {
                const int c = cn * BN + wn * 64 + nt * 8 + tg * 2;
                const float2 bv = *reinterpret_cast<const float2*>(cbias + c);
#pragma unroll
                for (int mt = 0; mt < 4; ++mt) {
                    red_add_v2(p[2 * mt] + c,
                               (C[mt][nt][0] + bv.x) * inv, (C[mt][nt][1] + bv.y) * inv);
                    red_add_v2(p[2 * mt + 1] + c,
                               (C[mt][nt][2] + bv.x) * inv, (C[mt][nt][3] + bv.y) * inv);
                }
            }
            // reset accumulators for the next tile
#pragma unroll
            for (int mt = 0; mt < 4; ++mt)
#pragma unroll
                for (int nt = 0; nt < 8; ++nt)
#pragma unroll
                    for (int v = 0; v < 4; ++v) C[mt][nt][v] = 0.0f;

            if (!nvalid) break;
            cA = nA; cW = nW; cbias = nbias; cids = nids; cout = nout; cm = nm; cn = nn;
        }
    }

    // ---- reset for next graph replay: last CTA to finish ----
    __syncthreads();
    if (tid == 0) {
        unsigned int old = atomicAdd(&g_fin, 1u);
        if (old == (unsigned)gridDim.x - 1u) {
            atomicExch(&g_tile, 0u);
            atomicExch(&g_fin, 0u);
        }
    }
}

// ---------------- launch ----------------

extern "C" void kernel_launch(void* const* d_in, const int* in_sizes, int n_in,
                              void* d_out, int out_size) {
    const float* nodes_emb = (const float*)d_in[0];
    const float* rels_emb  = (const float*)d_in[1];
    const int*   nodes_ids = (const int*)d_in[2];
    const int*   rels_ids  = (const int*)d_in[3];
    const float* ent_mem   = (const float*)d_in[4];
    const float* rel_mem   = (const float*)d_in[5];
    const float* W_node    = (const float*)d_in[6];
    const float* b_node    = (const float*)d_in[7];
    const float* W_rel     = (const float*)d_in[8];
    const float* b_rel     = (const float*)d_in[9];
    const int*   timep     = (const int*)d_in[10];
    float* out = (float*)d_out;

    static bool attr_set = false;
    if (!attr_set) {
        cudaFuncSetAttribute(gemm_scatter_kernel,
                             cudaFuncAttributeMaxDynamicSharedMemorySize, SMEM_BYTES);
        attr_set = true;
    }

    // 1) out = scaled concat of memories (sequential, HBM-peak ~57us)
    const long long TOT4 = ((long long)N_NODES * MEM_DIM + 500LL * MEM_DIM) / 4;
    const int blocks = (int)((TOT4 + 255) / 256);
    init_out_kernel<<<blocks, 256>>>((const float4*)ent_mem, (const float4*)rel_mem, timep,
                                     (float4*)out);

    // 2) persistent GEMM + scatter (work-stealing over 2048 tiles)
    gemm_scatter_kernel<<<PERSIST, THREADS, SMEM_BYTES>>>(
        nodes_emb, rels_emb, nodes_ids, rels_ids,
        W_node, b_node, W_rel, b_rel, timep, out);
}